// round 5
// baseline (speedup 1.0000x reference)
#include <cuda_runtime.h>
#include <cuda_fp16.h>
#include <cstdint>
#include <mma.h>

using namespace nvcuda;

// ---------------- problem constants ----------------
#define BATCH 1024
#define TSTEPS 256
#define DPART 64
#define ADIM 8
#define HDIM 256
#define KTOT 321
#define KPAD 336         // 256 h + 80 particle block (64 + 1 + 15 zero)
#define NPACK 1024       // 256 units * 4 panels (r, z, nf, hpn)

// cluster decomposition
#define CSIZE 8          // CTAs per cluster; each owns 128 packed cols (32 units)
#define NCLUST 16        // clusters; each owns 64 batch rows
#define MROWS 64
#define NCOLS 128
#define NTHREADS 512     // 16 warps

// SMEM strides (elements)
#define HS_LD 264        // halves (256 + 8)
#define PS_LD 88         // halves (80 + 8)
#define WS_LD 136        // halves (128 + 8)
#define CS_LD 132        // floats (128 + 4)

// SMEM byte offsets
#define SM_HS 0
#define SM_PS (2 * MROWS * HS_LD * 2)
#define SM_WS (SM_PS + MROWS * PS_LD * 2)
#define SM_CS (SM_WS + KPAD * WS_LD * 2)
#define SMEM_BYTES (SM_CS + MROWS * CS_LD * 4)   // ~204 KB

// ---------------- device scratch ----------------
__device__ __half g_Wph[KPAD * NPACK];     // packed fp16 GRU weights
__device__ __half g_hx[BATCH * HDIM];      // final h (fp16)
__device__ float  g_W1t[2 * 288 * 256];    // tf32-rounded W1, K padded to 288
__device__ float  g_W2t[2 * 256 * 256];    // tf32-rounded W2
__device__ float  g_mlp1[2 * BATCH * 256];
__device__ float  g_mlp2[2 * BATCH * 256];

// ---------------- GRU weight packing ----------------
__global__ void prep_weights(const float* __restrict__ Wi, const float* __restrict__ Wh) {
    int idx = blockIdx.x * blockDim.x + threadIdx.x;
    if (idx >= KPAD * NPACK) return;
    int k = idx / NPACK;
    int col = idx % NPACK;
    int hb = col >> 7;
    int rem = col & 127;
    int panel = rem >> 5;
    int u = rem & 31;
    int j = hb * 32 + u;
    float w = 0.0f;
    if (panel < 3) {
        int g = j + panel * 256;
        if (k < 256)          w = Wh[k * 768 + g];
        else if (k < KTOT)    w = Wi[(k - 256) * 768 + g];
    } else {
        if (k < 256)          w = Wh[k * 768 + (j + 512)];
    }
    g_Wph[idx] = __float2half(w);
}

// ---------------- MLP weight packing (tf32 rounding + zero pad) ----------------
__global__ void prep_mlp(const float* __restrict__ W1, const float* __restrict__ W2) {
    int idx = blockIdx.x * blockDim.x + threadIdx.x;
    const int N1 = 2 * 288 * 256;
    const int N2 = 2 * 256 * 256;
    if (idx < N1) {
        int c = idx / (288 * 256);
        int rem = idx % (288 * 256);
        int k = rem / 256, n = rem % 256;
        float w = (k < 265) ? W1[((size_t)c * 265 + k) * 256 + n] : 0.0f;
        g_W1t[idx] = wmma::__float_to_tf32(w);
    } else if (idx < N1 + N2) {
        int i2 = idx - N1;
        g_W2t[i2] = wmma::__float_to_tf32(W2[i2]);
    }
}

// ---------------- persistent GRU kernel ----------------
__global__ void __cluster_dims__(CSIZE, 1, 1) __launch_bounds__(NTHREADS, 1)
gru_persistent(const float* __restrict__ particles,   // [B,T,DP]
               const float* __restrict__ pweights,    // [B,T]
               const float* __restrict__ bi,          // [768]
               const float* __restrict__ bhn)         // [256]
{
    extern __shared__ char smem_raw[];
    __half* Hs = (__half*)(smem_raw + SM_HS);   // [2][MROWS][HS_LD]
    __half* Ps = (__half*)(smem_raw + SM_PS);   // [MROWS][PS_LD]
    __half* Ws = (__half*)(smem_raw + SM_WS);   // [KPAD][WS_LD]
    float*  Cs = (float*)(smem_raw + SM_CS);    // [MROWS][CS_LD]

    const int tid  = threadIdx.x;
    const int rnk  = blockIdx.x & (CSIZE - 1);
    const int cl   = blockIdx.x >> 3;
    const int row0 = cl * MROWS;
    const int col0 = rnk * NCOLS;

    const int warp = tid >> 5;
    const int wr   = warp & 3;     // row tile: rows wr*16
    const int wc   = warp >> 2;    // col group: cols wc*32 (2 tiles of 16)

    // epilogue mapping: unit pair up = tid&15 (units 2up, 2up+1), rows rb, rb+32
    const int up = tid & 15;
    const int rb = tid >> 4;
    const int j0 = rnk * 32 + up * 2;
    const float bir0 = bi[j0],       bir1 = bi[j0 + 1];
    const float biz0 = bi[256 + j0], biz1 = bi[256 + j0 + 1];
    const float bin0 = bi[512 + j0], bin1 = bi[512 + j0 + 1];
    const float bh0  = bhn[j0],      bh1  = bhn[j0 + 1];

    // shared-space u32 base of Hs (for mapa)
    unsigned int hs_u32;
    asm("{ .reg .u64 t; cvta.to.shared.u64 t, %1; cvt.u32.u64 %0, t; }"
        : "=r"(hs_u32) : "l"(Hs));

    // ---- load weight slice (once) ----
    for (int i = tid; i < KPAD * 16; i += NTHREADS) {
        int r = i >> 4, q = i & 15;
        ((uint4*)(Ws + r * WS_LD))[q] =
            ((const uint4*)(g_Wph + (size_t)r * NPACK + col0))[q];
    }
    // ---- zero Hs[0] h-columns ----
    for (int i = tid; i < MROWS * 32; i += NTHREADS) {
        int r = i >> 5, q = i & 31;
        ((uint4*)(Hs + r * HS_LD))[q] = make_uint4(0, 0, 0, 0);
    }
    // ---- zero all of Ps (cols 65..87 stay zero forever) ----
    for (int i = tid; i < MROWS * 11; i += NTHREADS) {
        int r = i / 11, q = i % 11;
        ((uint4*)(Ps + r * PS_LD))[q] = make_uint4(0, 0, 0, 0);
    }
    __syncthreads();
    asm volatile("barrier.cluster.arrive.aligned;" ::: "memory");
    asm volatile("barrier.cluster.wait.aligned;" ::: "memory");

    for (int t = 0; t < TSTEPS; ++t) {
        const int p = t & 1;
        const __half* __restrict__ Hin = Hs + p * MROWS * HS_LD;

        // ---- fill particle tile for step t ----
        for (int i = tid; i < MROWS * 16; i += NTHREADS) {
            int r = i >> 4, q = i & 15;
            float4 v = ((const float4*)(particles +
                        ((size_t)(row0 + r) * TSTEPS + t) * DPART))[q];
            __half2* dst = (__half2*)(Ps + r * PS_LD + q * 4);
            dst[0] = __floats2half2_rn(v.x, v.y);
            dst[1] = __floats2half2_rn(v.z, v.w);
        }
        if (tid < MROWS)
            Ps[tid * PS_LD + 64] = __float2half(pweights[(size_t)(row0 + tid) * TSTEPS + t]);
        __syncthreads();

        // ---- GEMM: C[64,128] = [Hin | Ps] @ Ws  (fp16 in, fp32 acc) ----
        wmma::fragment<wmma::accumulator, 16, 16, 16, float> acc[2];
        wmma::fill_fragment(acc[0], 0.0f);
        wmma::fill_fragment(acc[1], 0.0f);

#pragma unroll
        for (int kk = 0; kk < 256; kk += 16) {
            wmma::fragment<wmma::matrix_a, 16, 16, 16, __half, wmma::row_major> af;
            wmma::load_matrix_sync(af, Hin + (wr * 16) * HS_LD + kk, HS_LD);
#pragma unroll
            for (int ct = 0; ct < 2; ct++) {
                wmma::fragment<wmma::matrix_b, 16, 16, 16, __half, wmma::row_major> bf;
                wmma::load_matrix_sync(bf, Ws + kk * WS_LD + wc * 32 + ct * 16, WS_LD);
                wmma::mma_sync(acc[ct], af, bf, acc[ct]);
            }
        }
#pragma unroll
        for (int kk = 0; kk < 80; kk += 16) {
            wmma::fragment<wmma::matrix_a, 16, 16, 16, __half, wmma::row_major> af;
            wmma::load_matrix_sync(af, Ps + (wr * 16) * PS_LD + kk, PS_LD);
#pragma unroll
            for (int ct = 0; ct < 2; ct++) {
                wmma::fragment<wmma::matrix_b, 16, 16, 16, __half, wmma::row_major> bf;
                wmma::load_matrix_sync(bf, Ws + (256 + kk) * WS_LD + wc * 32 + ct * 16, WS_LD);
                wmma::mma_sync(acc[ct], af, bf, acc[ct]);
            }
        }
#pragma unroll
        for (int ct = 0; ct < 2; ct++)
            wmma::store_matrix_sync(Cs + (wr * 16) * CS_LD + wc * 32 + ct * 16,
                                    acc[ct], CS_LD, wmma::mem_row_major);
        __syncthreads();

        // ---- fused gate epilogue + DSMEM scatter of h_{t+1} to all 8 CTAs ----
        const unsigned int out_base = hs_u32 +
            (unsigned int)((p ^ 1) * MROWS * HS_LD) * 2u;
#pragma unroll
        for (int rr = 0; rr < 2; ++rr) {
            const int r = rb + rr * 32;
            const float* Crow = Cs + r * CS_LD;
            float cr0  = Crow[up * 2],       cr1  = Crow[up * 2 + 1];
            float cz0  = Crow[32 + up * 2],  cz1  = Crow[32 + up * 2 + 1];
            float cn0  = Crow[64 + up * 2],  cn1  = Crow[64 + up * 2 + 1];
            float hp0  = Crow[96 + up * 2],  hp1  = Crow[96 + up * 2 + 1];
            float rg0 = __fdividef(1.0f, 1.0f + __expf(-(cr0 + bir0)));
            float rg1 = __fdividef(1.0f, 1.0f + __expf(-(cr1 + bir1)));
            float zg0 = __fdividef(1.0f, 1.0f + __expf(-(cz0 + biz0)));
            float zg1 = __fdividef(1.0f, 1.0f + __expf(-(cz1 + biz1)));
            float a0 = (cn0 + bin0 - hp0) + rg0 * (hp0 + bh0);
            float a1 = (cn1 + bin1 - hp1) + rg1 * (hp1 + bh1);
            a0 = fminf(fmaxf(a0, -15.0f), 15.0f);
            a1 = fminf(fmaxf(a1, -15.0f), 15.0f);
            float e0 = __expf(-2.0f * a0), e1 = __expf(-2.0f * a1);
            float ng0 = __fdividef(1.0f - e0, 1.0f + e0);
            float ng1 = __fdividef(1.0f - e1, 1.0f + e1);
            __half2 hold = *(const __half2*)(Hin + r * HS_LD + j0);
            float ho0 = __low2float(hold), ho1 = __high2float(hold);
            float hn0 = (1.0f - zg0) * ng0 + zg0 * ho0;
            float hn1 = (1.0f - zg1) * ng1 + zg1 * ho1;
            __half2 hv = __floats2half2_rn(hn0, hn1);
            unsigned int val = *(unsigned int*)&hv;
            unsigned int off = out_base + (unsigned int)(r * HS_LD + j0) * 2u;
#pragma unroll
            for (int d = 0; d < CSIZE; ++d) {
                unsigned int rem;
                asm("mapa.shared::cluster.u32 %0, %1, %2;" : "=r"(rem) : "r"(off), "r"(d));
                asm volatile("st.shared::cluster.b32 [%0], %1;" :: "r"(rem), "r"(val) : "memory");
            }
            if (t == TSTEPS - 1)
                *(__half2*)(g_hx + (size_t)(row0 + r) * HDIM + j0) = hv;
        }

        // release scatter / acquire peers' scatters
        asm volatile("barrier.cluster.arrive.aligned;" ::: "memory");
        asm volatile("barrier.cluster.wait.aligned;" ::: "memory");
    }
}

// ---------------- MLP layers: tf32 wmma, 64x64 tile, BK=32 ----------------
__global__ void __launch_bounds__(256) mlp_layer_t(
    const float* __restrict__ action, const float* __restrict__ time_idx,
    const float* __restrict__ bias, int KP, int mode)
{
    __shared__ float As[64][40];
    __shared__ float Bs[32][72];
    __shared__ float stage[64][68];

    const int c = blockIdx.z;
    const int rowb = blockIdx.x * 64;
    const int colb = blockIdx.y * 64;
    const int tid = threadIdx.x;
    const int warp = tid >> 5;
    const int wr = warp & 3;
    const int wc = warp >> 2;      // {0,1}

    wmma::fragment<wmma::accumulator, 16, 16, 8, float> acc[2];
    wmma::fill_fragment(acc[0], 0.0f);
    wmma::fill_fragment(acc[1], 0.0f);

    const float* Wsrc = (mode == 0) ? g_W1t + (size_t)c * 288 * 256
                                    : g_W2t + (size_t)c * 256 * 256;

    for (int k0 = 0; k0 < KP; k0 += 32) {
        for (int i = tid; i < 64 * 32; i += 256) {
            int r = i >> 5, k = i & 31;
            int d = k0 + k;
            float v = 0.0f;
            if (mode == 0) {
                if (d < 256)       v = __half2float(g_hx[(size_t)(rowb + r) * HDIM + d]);
                else if (d < 264)  v = action[(rowb + r) * ADIM + (d - 256)];
                else if (d == 264) v = time_idx[rowb + r] * 0.01f;
            } else {
                v = g_mlp1[((size_t)c * BATCH + rowb + r) * 256 + d];
            }
            As[r][k] = wmma::__float_to_tf32(v);
        }
        for (int i = tid; i < 32 * 64; i += 256) {
            int kk = i >> 6, cc = i & 63;
            Bs[kk][cc] = Wsrc[(size_t)(k0 + kk) * 256 + colb + cc];
        }
        __syncthreads();
#pragma unroll
        for (int kk = 0; kk < 32; kk += 8) {
            wmma::fragment<wmma::matrix_a, 16, 16, 8, wmma::precision::tf32, wmma::row_major> af;
            wmma::load_matrix_sync(af, &As[wr * 16][kk], 40);
#pragma unroll
            for (int ct = 0; ct < 2; ct++) {
                wmma::fragment<wmma::matrix_b, 16, 16, 8, wmma::precision::tf32, wmma::row_major> bf;
                wmma::load_matrix_sync(bf, &Bs[kk][wc * 32 + ct * 16], 72);
                wmma::mma_sync(acc[ct], af, bf, acc[ct]);
            }
        }
        __syncthreads();
    }

#pragma unroll
    for (int ct = 0; ct < 2; ct++)
        wmma::store_matrix_sync(&stage[wr * 16][wc * 32 + ct * 16], acc[ct], 68,
                                wmma::mem_row_major);
    __syncthreads();

    float* dst = (mode == 0) ? g_mlp1 : g_mlp2;
    for (int i = tid; i < 64 * 64; i += 256) {
        int r = i >> 6, col = i & 63;
        float v = stage[r][col] + bias[c * 256 + colb + col];
        dst[((size_t)c * BATCH + rowb + r) * 256 + colb + col] = fmaxf(v, 0.0f);
    }
}

// ---------------- final projection ----------------
__global__ void mlp_out(const float* __restrict__ W3, const float* __restrict__ b3,
                        float* __restrict__ out)
{
    int gw   = (blockIdx.x * blockDim.x + threadIdx.x) >> 5;
    int lane = threadIdx.x & 31;
    if (gw >= 2 * BATCH) return;
    int c = gw >> 10;
    int b = gw & 1023;
    const float* v = g_mlp2 + ((size_t)c * BATCH + b) * 256;
    const float* w = W3 + (size_t)c * 256;
    float s = 0.0f;
    for (int i = lane; i < 256; i += 32) s += v[i] * w[i];
#pragma unroll
    for (int o = 16; o; o >>= 1) s += __shfl_xor_sync(0xffffffffu, s, o);
    if (lane == 0) out[b * 2 + c] = s + b3[c];
}

// ---------------- launch ----------------
extern "C" void kernel_launch(void* const* d_in, const int* in_sizes, int n_in,
                              void* d_out, int out_size)
{
    const float* particles = (const float*)d_in[0];
    const float* weights   = (const float*)d_in[1];
    const float* action    = (const float*)d_in[2];
    const float* time_idx  = (const float*)d_in[3];
    const float* Wi        = (const float*)d_in[4];
    const float* bi        = (const float*)d_in[5];
    const float* Wh        = (const float*)d_in[6];
    const float* bhn       = (const float*)d_in[7];
    const float* W1        = (const float*)d_in[8];
    const float* b1        = (const float*)d_in[9];
    const float* W2        = (const float*)d_in[10];
    const float* b2        = (const float*)d_in[11];
    const float* W3        = (const float*)d_in[12];
    const float* b3        = (const float*)d_in[13];
    float* out = (float*)d_out;

    cudaFuncSetAttribute(gru_persistent,
                         cudaFuncAttributeMaxDynamicSharedMemorySize, SMEM_BYTES);

    prep_weights<<<(KPAD * NPACK + 255) / 256, 256>>>(Wi, Wh);
    prep_mlp<<<(2 * 288 * 256 + 2 * 256 * 256 + 255) / 256, 256>>>(W1, W2);

    gru_persistent<<<NCLUST * CSIZE, NTHREADS, SMEM_BYTES>>>(particles, weights, bi, bhn);

    mlp_layer_t<<<dim3(16, 4, 2), 256>>>(action, time_idx, b1, 288, 0);
    mlp_layer_t<<<dim3(16, 4, 2), 256>>>(action, time_idx, b2, 256, 1);
    mlp_out<<<(2 * BATCH * 32 + 255) / 256, 256>>>(W3, b3, out);
}